// round 16
// baseline (speedup 1.0000x reference)
#include <cuda_runtime.h>
#include <math.h>

#define S_LEN 4096
#define BATCH 16
#define H2DIM 1024
#define NBLK 152
#define CHUNK 27                                  // ceil(4096/152)
#define ROW_BYTES (BATCH * H2DIM * 4)             // 64KB per full s-row
#define SLICE_BYTES (H2DIM * 4)                   // 4KB per (s,b) slice
#define NSTAGE 3
// mainpass CTA: 8 warps, half-row slots of 32KB
#define HROW_BYTES (8 * SLICE_BYTES)              // 32KB per (s, batch-half)
#define MBAR_OFF (NSTAGE * HROW_BYTES)            // after 96KB
#define MAIN_SMEM (MBAR_OFF + 8 * NSTAGE * 8)     // + 8 warps * 3 mbars

// Scratch (allocation-free contract)
__device__ float g_alt[BATCH * H2DIM];            // altered_state (+bias)
__device__ float g_wraw[BATCH * S_LEN];
__device__ float g_m[NBLK * BATCH];
__device__ float g_l[NBLK * BATCH];
__device__ float g_acc[(size_t)NBLK * BATCH * H2DIM];

// ---- packed f32x2 helpers ----------------------------------------------------
__device__ __forceinline__ unsigned long long fma2(unsigned long long a,
                                                   unsigned long long b,
                                                   unsigned long long c) {
    unsigned long long d;
    asm("fma.rn.f32x2 %0, %1, %2, %3;" : "=l"(d) : "l"(a), "l"(b), "l"(c));
    return d;
}
__device__ __forceinline__ unsigned long long mul2(unsigned long long a,
                                                   unsigned long long b) {
    unsigned long long d;
    asm("mul.rn.f32x2 %0, %1, %2;" : "=l"(d) : "l"(a), "l"(b));
    return d;
}
__device__ __forceinline__ unsigned long long pk2(float lo, float hi) {
    unsigned long long r;
    asm("mov.b64 %0, {%1, %2};" : "=l"(r) : "f"(lo), "f"(hi));
    return r;
}
__device__ __forceinline__ float2 upk2(unsigned long long v) {
    float2 r;
    asm("mov.b64 {%0, %1}, %2;" : "=f"(r.x), "=f"(r.y) : "l"(v));
    return r;
}
__device__ __forceinline__ float warp_sum(float v) {
#pragma unroll
    for (int off = 16; off > 0; off >>= 1)
        v += __shfl_xor_sync(0xffffffffu, v, off);
    return v;
}

__device__ __forceinline__ void mbar_wait(unsigned mb, int par) {
    asm volatile(
        "{\n\t.reg .pred P1;\n\t"
        "W0_%=:\n\t"
        "mbarrier.try_wait.parity.acquire.cta.shared::cta.b64 P1, [%0], %1, 0x989680;\n\t"
        "@P1 bra.uni W1_%=;\n\t"
        "bra.uni W0_%=;\n\t"
        "W1_%=:\n\t}"
        :: "r"(mb), "r"(par) : "memory");
}

__device__ __forceinline__ void tma_slice(unsigned sdst, const char* gsrc, unsigned mb) {
    asm volatile("mbarrier.arrive.expect_tx.shared.b64 _, [%0], %1;"
                 :: "r"(mb), "r"(SLICE_BYTES) : "memory");
    asm volatile(
        "cp.async.bulk.shared::cluster.global.mbarrier::complete_tx::bytes "
        "[%0], [%1], %2, [%3];"
        :: "r"(sdst), "l"(gsrc), "r"(SLICE_BYTES), "r"(mb) : "memory");
}

// ---------------------------------------------------------------------------
// Kernel 1: altered_state = state @ attn_w^T + attn_b  (exact R3 design)
// grid=256, block=256 (8 warps). Warp handles row r for 8 batches.
// ---------------------------------------------------------------------------
__global__ void __launch_bounds__(256, 2)
k_altered(const float* __restrict__ state,
          const float* __restrict__ attn_w,
          const float* __restrict__ attn_b)
{
    const int tid = threadIdx.x;
    const int wid = tid >> 5, lane = tid & 31;
    const int r = blockIdx.x * 4 + (wid >> 1);
    const int bg = (wid & 1) * 8;                 // batch group: 0 or 8

    const float4* wr = (const float4*)(attn_w + (size_t)r * H2DIM);
    ulonglong2 wv[8];
#pragma unroll
    for (int k = 0; k < 8; k++) {
        float4 v = __ldg(wr + lane + 32 * k);
        wv[k] = *(ulonglong2*)&v;
    }
    const float bias = __ldg(attn_b + r);

    float res[8];
#pragma unroll
    for (int bb = 0; bb < 8; bb++) {
        const float4* sp = (const float4*)(state + (size_t)(bg + bb) * H2DIM);
        unsigned long long a2 = 0ull;
#pragma unroll
        for (int k = 0; k < 8; k++) {
            float4 s = __ldg(sp + lane + 32 * k);
            ulonglong2 s2 = *(ulonglong2*)&s;
            a2 = fma2(wv[k].x, s2.x, a2);
            a2 = fma2(wv[k].y, s2.y, a2);
        }
        float2 f = upk2(a2);
        float p = f.x + f.y;
        p = warp_sum(p);
        res[bb] = p + bias;
    }
    if (lane == 0) {
#pragma unroll
        for (int bb = 0; bb < 8; bb++)
            g_alt[(size_t)(bg + bb) * H2DIM + r] = res[bb];
    }
}

// ---------------------------------------------------------------------------
// Kernel 2: single-pass online softmax, per-warp TMA rings.
// grid = (152, 2), block = 256 (8 warps) -> 2 CTAs/SM, 32 warps/SM.
// CTA (c, bg): rows [c*27, ...), batches bg*8 .. bg*8+7. Warp wid owns
// batch b = bg*8 + wid with its private 3-slot ring (4KB slices).
// ---------------------------------------------------------------------------
__global__ void __launch_bounds__(256, 2)
k_mainpass(const float* __restrict__ enc)
{
    extern __shared__ char smem[];
    const int tid = threadIdx.x;
    const int wid = tid >> 5;
    const int lane = tid & 31;
    const int c = blockIdx.x;
    const int b = blockIdx.y * 8 + wid;
    const int s0 = c * CHUNK;
    const int s1 = min(s0 + CHUNK, S_LEN);
    const int n = max(s1 - s0, 0);

    const unsigned smem_u = (unsigned)__cvta_generic_to_shared(smem);
    const unsigned slice0 = smem_u + wid * SLICE_BYTES;
    const unsigned mbar0 = smem_u + MBAR_OFF + wid * (NSTAGE * 8);
    const char* gbase = (const char*)enc + (size_t)b * SLICE_BYTES;

    if (lane == 0) {
#pragma unroll
        for (int k = 0; k < NSTAGE; k++)
            asm volatile("mbarrier.init.shared.b64 [%0], 1;"
                         :: "r"(mbar0 + k * 8) : "memory");
        asm volatile("fence.proxy.async.shared::cta;" ::: "memory");
#pragma unroll
        for (int k = 0; k < NSTAGE; k++)
            if (k < n)
                tma_slice(slice0 + k * HROW_BYTES,
                          gbase + (size_t)(s0 + k) * ROW_BYTES, mbar0 + k * 8);
    }

    // alt slice (overlaps TMA prologue)
    unsigned long long alt2[16];
    {
        const float4* ap = (const float4*)(g_alt + (size_t)b * H2DIM);
#pragma unroll
        for (int k = 0; k < 8; k++) {
            float4 v = __ldg(ap + lane + 32 * k);
            ulonglong2 t = *(ulonglong2*)&v;
            alt2[2 * k] = t.x;
            alt2[2 * k + 1] = t.y;
        }
    }

    unsigned long long acc2[16];
#pragma unroll
    for (int j = 0; j < 16; j++) acc2[j] = 0ull;
    float m = -1e30f, l = 0.f;

    int slot = 0, par = 0;
    for (int i = 0; i < n; i++) {
        const unsigned mb = mbar0 + slot * 8;
        mbar_wait(mb, par);

        const ulonglong2* bp = (const ulonglong2*)(smem + slot * HROW_BYTES
                                                   + wid * SLICE_BYTES);
        ulonglong2 e2[8];
#pragma unroll
        for (int k = 0; k < 8; k++) e2[k] = bp[lane + 32 * k];

        int nxt = i + NSTAGE;
        if (nxt < n && lane == 0)
            tma_slice(slice0 + slot * HROW_BYTES,
                      gbase + (size_t)(s0 + nxt) * ROW_BYTES, mb);

        unsigned long long w2 = 0ull;
#pragma unroll
        for (int k = 0; k < 8; k++) {
            w2 = fma2(e2[k].x, alt2[2 * k], w2);
            w2 = fma2(e2[k].y, alt2[2 * k + 1], w2);
        }
        float2 wp2 = upk2(w2);
        float w = warp_sum(wp2.x + wp2.y);

        if (w > m) {                               // warp-uniform
            float sc = __expf(m - w);
            m = w;
            l *= sc;
            unsigned long long sc2 = pk2(sc, sc);
#pragma unroll
            for (int j = 0; j < 16; j++) acc2[j] = mul2(acc2[j], sc2);
        }
        float p = __expf(w - m);
        l += p;
        unsigned long long p2 = pk2(p, p);
#pragma unroll
        for (int k = 0; k < 8; k++) {
            acc2[2 * k]     = fma2(p2, e2[k].x, acc2[2 * k]);
            acc2[2 * k + 1] = fma2(p2, e2[k].y, acc2[2 * k + 1]);
        }
        if (lane == 0) g_wraw[b * S_LEN + s0 + i] = w;

        if (++slot == NSTAGE) { slot = 0; par ^= 1; }
    }

    if (lane == 0) {
        g_m[c * BATCH + b] = m;
        g_l[c * BATCH + b] = l;
    }
    float4* outp = (float4*)(g_acc + ((size_t)c * BATCH + b) * H2DIM);
#pragma unroll
    for (int k = 0; k < 8; k++) {
        float2 a = upk2(acc2[2 * k]);
        float2 bq = upk2(acc2[2 * k + 1]);
        outp[lane + 32 * k] = make_float4(a.x, a.y, bq.x, bq.y);
    }
}

// ---------------------------------------------------------------------------
// Kernel 3: finish. grid = (BATCH, 24), block 512.
// t in [0,16): attention_applied d-tile of 64, 8 parallel c2-groups (19 each).
// t in [16,24): normalized_weights s-tile of 512.
// ---------------------------------------------------------------------------
__global__ void __launch_bounds__(512, 2)
k_finish(float* __restrict__ out)
{
    const int b = blockIdx.x;
    const int t = blockIdx.y;
    const int tid = threadIdx.x;
    __shared__ float sM, sInvL;
    __shared__ float s_coef[NBLK];
    __shared__ float s_part[512];

    if (tid < 32) {
        float mx = -1e30f;
        for (int c2 = tid; c2 < NBLK; c2 += 32)
            mx = fmaxf(mx, g_m[c2 * BATCH + b]);
#pragma unroll
        for (int off = 16; off > 0; off >>= 1)
            mx = fmaxf(mx, __shfl_xor_sync(0xffffffffu, mx, off));
        float ls = 0.f;
        for (int c2 = tid; c2 < NBLK; c2 += 32)
            ls += __expf(g_m[c2 * BATCH + b] - mx) * g_l[c2 * BATCH + b];
        ls = warp_sum(ls);
        if (tid == 0) { sM = mx; sInvL = 1.f / ls; }
    }
    __syncthreads();
    const float M = sM, invL = sInvL;

    if (t < 16) {
        if (tid < NBLK) s_coef[tid] = __expf(g_m[tid * BATCH + b] - M);
        __syncthreads();
        const int doff = tid & 63;
        const int g = tid >> 6;                 // 0..7
        const int d = t * 64 + doff;
        float a = 0.f;
#pragma unroll
        for (int k = 0; k < 19; k++) {          // 152 = 8 * 19
            int c2 = g + 8 * k;
            a = fmaf(s_coef[c2], g_acc[((size_t)c2 * BATCH + b) * H2DIM + d], a);
        }
        s_part[tid] = a;
        __syncthreads();
        if (tid < 64) {
            float v = 0.f;
#pragma unroll
            for (int gg = 0; gg < 8; gg++) v += s_part[gg * 64 + tid];
            out[b * H2DIM + d] = v * invL;
        }
    } else {
        const int s = (t - 16) * 512 + tid;
        out[BATCH * H2DIM + b * S_LEN + s] =
            __expf(g_wraw[b * S_LEN + s] - M) * invL;
    }
}

// ---------------------------------------------------------------------------
extern "C" void kernel_launch(void* const* d_in, const int* in_sizes, int n_in,
                              void* d_out, int out_size)
{
    const float* enc    = (const float*)d_in[0];
    const float* state  = (const float*)d_in[1];
    const float* attn_w = (const float*)d_in[3];
    const float* attn_b = (const float*)d_in[4];
    float* out = (float*)d_out;

    cudaFuncSetAttribute(k_mainpass,
        cudaFuncAttributeMaxDynamicSharedMemorySize, MAIN_SMEM);

    k_altered<<<256, 256>>>(state, attn_w, attn_b);
    k_mainpass<<<dim3(NBLK, 2), 256, MAIN_SMEM>>>(enc);
    k_finish<<<dim3(BATCH, 24), 512>>>(out);
}

// round 17
// speedup vs baseline: 1.0239x; 1.0239x over previous
#include <cuda_runtime.h>
#include <math.h>

#define S_LEN 4096
#define BATCH 16
#define H2DIM 1024
#define NBLK 152
#define CHUNK 27                                  // ceil(4096/152)
#define ROW_BYTES (BATCH * H2DIM * 4)             // 64KB per s-row
#define SLICE_BYTES (H2DIM * 4)                   // 4KB per (s,b) slice
#define NSTAGE 3
#define MBAR_OFF (NSTAGE * ROW_BYTES)
#define MAIN_SMEM (MBAR_OFF + 16 * NSTAGE * 8)

// Scratch (allocation-free contract)
__device__ float g_alt[BATCH * H2DIM];            // altered_state (+bias)
__device__ float g_wraw[BATCH * S_LEN];
__device__ float g_m[NBLK * BATCH];
__device__ float g_l[NBLK * BATCH];
__device__ float g_acc[(size_t)NBLK * BATCH * H2DIM];

// ---- packed f32x2 helpers ----------------------------------------------------
__device__ __forceinline__ unsigned long long fma2(unsigned long long a,
                                                   unsigned long long b,
                                                   unsigned long long c) {
    unsigned long long d;
    asm("fma.rn.f32x2 %0, %1, %2, %3;" : "=l"(d) : "l"(a), "l"(b), "l"(c));
    return d;
}
__device__ __forceinline__ unsigned long long mul2(unsigned long long a,
                                                   unsigned long long b) {
    unsigned long long d;
    asm("mul.rn.f32x2 %0, %1, %2;" : "=l"(d) : "l"(a), "l"(b));
    return d;
}
__device__ __forceinline__ unsigned long long pk2(float lo, float hi) {
    unsigned long long r;
    asm("mov.b64 %0, {%1, %2};" : "=l"(r) : "f"(lo), "f"(hi));
    return r;
}
__device__ __forceinline__ float2 upk2(unsigned long long v) {
    float2 r;
    asm("mov.b64 {%0, %1}, %2;" : "=f"(r.x), "=f"(r.y) : "l"(v));
    return r;
}
__device__ __forceinline__ float warp_sum(float v) {
#pragma unroll
    for (int off = 16; off > 0; off >>= 1)
        v += __shfl_xor_sync(0xffffffffu, v, off);
    return v;
}

__device__ __forceinline__ void mbar_wait(unsigned mb, int par) {
    asm volatile(
        "{\n\t.reg .pred P1;\n\t"
        "W0_%=:\n\t"
        "mbarrier.try_wait.parity.acquire.cta.shared::cta.b64 P1, [%0], %1, 0x989680;\n\t"
        "@P1 bra.uni W1_%=;\n\t"
        "bra.uni W0_%=;\n\t"
        "W1_%=:\n\t}"
        :: "r"(mb), "r"(par) : "memory");
}

__device__ __forceinline__ void tma_slice(unsigned sdst, const char* gsrc, unsigned mb) {
    asm volatile("mbarrier.arrive.expect_tx.shared.b64 _, [%0], %1;"
                 :: "r"(mb), "r"(SLICE_BYTES) : "memory");
    asm volatile(
        "cp.async.bulk.shared::cluster.global.mbarrier::complete_tx::bytes "
        "[%0], [%1], %2, [%3];"
        :: "r"(sdst), "l"(gsrc), "r"(SLICE_BYTES), "r"(mb) : "memory");
}

// ---------------------------------------------------------------------------
// Kernel 1: altered_state = state @ attn_w^T + attn_b  (R16 design, 7.3us)
// grid=256, block=256 (8 warps). Warp handles row r for 8 batches.
// ---------------------------------------------------------------------------
__global__ void __launch_bounds__(256, 2)
k_altered(const float* __restrict__ state,
          const float* __restrict__ attn_w,
          const float* __restrict__ attn_b)
{
    const int tid = threadIdx.x;
    const int wid = tid >> 5, lane = tid & 31;
    const int r = blockIdx.x * 4 + (wid >> 1);
    const int bg = (wid & 1) * 8;                 // batch group: 0 or 8

    const float4* wr = (const float4*)(attn_w + (size_t)r * H2DIM);
    ulonglong2 wv[8];
#pragma unroll
    for (int k = 0; k < 8; k++) {
        float4 v = __ldg(wr + lane + 32 * k);
        wv[k] = *(ulonglong2*)&v;
    }
    const float bias = __ldg(attn_b + r);

    float res[8];
#pragma unroll
    for (int bb = 0; bb < 8; bb++) {
        const float4* sp = (const float4*)(state + (size_t)(bg + bb) * H2DIM);
        unsigned long long a2 = 0ull;
#pragma unroll
        for (int k = 0; k < 8; k++) {
            float4 s = __ldg(sp + lane + 32 * k);
            ulonglong2 s2 = *(ulonglong2*)&s;
            a2 = fma2(wv[k].x, s2.x, a2);
            a2 = fma2(wv[k].y, s2.y, a2);
        }
        float2 f = upk2(a2);
        float p = warp_sum(f.x + f.y);
        res[bb] = p + bias;
    }
    if (lane == 0) {
#pragma unroll
        for (int bb = 0; bb < 8; bb++)
            g_alt[(size_t)(bg + bb) * H2DIM + r] = res[bb];
    }
}

// ---------------------------------------------------------------------------
// Kernel 2: single-pass online softmax, per-warp TMA rings (R4 structure).
// Launched with Programmatic Stream Serialization: prologue TMA (enc, does
// NOT depend on g_alt) is issued BEFORE cudaGridDependencySynchronize().
// grid=152, block=512, warp b owns batch b.
// ---------------------------------------------------------------------------
__global__ void __launch_bounds__(512, 1)
k_mainpass(const float* __restrict__ enc)
{
    extern __shared__ char smem[];
    const int tid = threadIdx.x;
    const int b = tid >> 5;
    const int lane = tid & 31;
    const int c = blockIdx.x;
    const int s0 = c * CHUNK;
    const int s1 = min(s0 + CHUNK, S_LEN);
    const int n = max(s1 - s0, 0);

    const unsigned smem_u = (unsigned)__cvta_generic_to_shared(smem);
    const unsigned slice0 = smem_u + b * SLICE_BYTES;
    const unsigned mbar0 = smem_u + MBAR_OFF + b * (NSTAGE * 8);
    const char* gbase = (const char*)enc + (size_t)b * SLICE_BYTES;

    if (lane == 0) {
#pragma unroll
        for (int k = 0; k < NSTAGE; k++)
            asm volatile("mbarrier.init.shared.b64 [%0], 1;"
                         :: "r"(mbar0 + k * 8) : "memory");
        asm volatile("fence.proxy.async.shared::cta;" ::: "memory");
#pragma unroll
        for (int k = 0; k < NSTAGE; k++)
            if (k < n)
                tma_slice(slice0 + k * ROW_BYTES,
                          gbase + (size_t)(s0 + k) * ROW_BYTES, mbar0 + k * 8);
    }

    // Wait for k_altered's g_alt writes to be visible (PDL dependency).
    cudaGridDependencySynchronize();

    unsigned long long alt2[16];
    {
        const float4* ap = (const float4*)(g_alt + b * H2DIM);
#pragma unroll
        for (int k = 0; k < 8; k++) {
            float4 v = __ldg(ap + lane + 32 * k);
            ulonglong2 t = *(ulonglong2*)&v;
            alt2[2 * k] = t.x;
            alt2[2 * k + 1] = t.y;
        }
    }

    unsigned long long acc2[16];
#pragma unroll
    for (int j = 0; j < 16; j++) acc2[j] = 0ull;
    float m = -1e30f, l = 0.f;

    int slot = 0, par = 0;
    for (int i = 0; i < n; i++) {
        const unsigned mb = mbar0 + slot * 8;
        mbar_wait(mb, par);

        const ulonglong2* bp = (const ulonglong2*)(smem + slot * ROW_BYTES
                                                   + b * SLICE_BYTES);
        ulonglong2 e2[8];
#pragma unroll
        for (int k = 0; k < 8; k++) e2[k] = bp[lane + 32 * k];

        int nxt = i + NSTAGE;
        if (nxt < n && lane == 0)
            tma_slice(slice0 + slot * ROW_BYTES,
                      gbase + (size_t)(s0 + nxt) * ROW_BYTES, mb);

        unsigned long long w2 = 0ull;
#pragma unroll
        for (int k = 0; k < 8; k++) {
            w2 = fma2(e2[k].x, alt2[2 * k], w2);
            w2 = fma2(e2[k].y, alt2[2 * k + 1], w2);
        }
        float2 wp2 = upk2(w2);
        float w = warp_sum(wp2.x + wp2.y);

        if (w > m) {                               // warp-uniform
            float sc = __expf(m - w);
            m = w;
            l *= sc;
            unsigned long long sc2 = pk2(sc, sc);
#pragma unroll
            for (int j = 0; j < 16; j++) acc2[j] = mul2(acc2[j], sc2);
        }
        float p = __expf(w - m);
        l += p;
        unsigned long long p2 = pk2(p, p);
#pragma unroll
        for (int k = 0; k < 8; k++) {
            acc2[2 * k]     = fma2(p2, e2[k].x, acc2[2 * k]);
            acc2[2 * k + 1] = fma2(p2, e2[k].y, acc2[2 * k + 1]);
        }
        if (lane == 0) g_wraw[b * S_LEN + s0 + i] = w;

        if (++slot == NSTAGE) { slot = 0; par ^= 1; }
    }

    if (lane == 0) {
        g_m[c * BATCH + b] = m;
        g_l[c * BATCH + b] = l;
    }
    float4* outp = (float4*)(g_acc + ((size_t)c * BATCH + b) * H2DIM);
#pragma unroll
    for (int k = 0; k < 8; k++) {
        float2 a = upk2(acc2[2 * k]);
        float2 bq = upk2(acc2[2 * k + 1]);
        outp[lane + 32 * k] = make_float4(a.x, a.y, bq.x, bq.y);
    }
}

// ---------------------------------------------------------------------------
// Kernel 3: finish. grid = (BATCH, 24), block 512.
// ---------------------------------------------------------------------------
__global__ void __launch_bounds__(512, 2)
k_finish(float* __restrict__ out)
{
    const int b = blockIdx.x;
    const int t = blockIdx.y;
    const int tid = threadIdx.x;
    __shared__ float sM, sInvL;
    __shared__ float s_coef[NBLK];
    __shared__ float s_part[512];

    if (tid < 32) {
        float mx = -1e30f;
        for (int c2 = tid; c2 < NBLK; c2 += 32)
            mx = fmaxf(mx, g_m[c2 * BATCH + b]);
#pragma unroll
        for (int off = 16; off > 0; off >>= 1)
            mx = fmaxf(mx, __shfl_xor_sync(0xffffffffu, mx, off));
        float ls = 0.f;
        for (int c2 = tid; c2 < NBLK; c2 += 32)
            ls += __expf(g_m[c2 * BATCH + b] - mx) * g_l[c2 * BATCH + b];
        ls = warp_sum(ls);
        if (tid == 0) { sM = mx; sInvL = 1.f / ls; }
    }
    __syncthreads();
    const float M = sM, invL = sInvL;

    if (t < 16) {
        if (tid < NBLK) s_coef[tid] = __expf(g_m[tid * BATCH + b] - M);
        __syncthreads();
        const int doff = tid & 63;
        const int g = tid >> 6;                 // 0..7
        const int d = t * 64 + doff;
        float a = 0.f;
#pragma unroll
        for (int k = 0; k < 19; k++) {          // 152 = 8 * 19
            int c2 = g + 8 * k;
            a = fmaf(s_coef[c2], g_acc[((size_t)c2 * BATCH + b) * H2DIM + d], a);
        }
        s_part[tid] = a;
        __syncthreads();
        if (tid < 64) {
            float v = 0.f;
#pragma unroll
            for (int gg = 0; gg < 8; gg++) v += s_part[gg * 64 + tid];
            out[b * H2DIM + d] = v * invL;
        }
    } else {
        const int s = (t - 16) * 512 + tid;
        out[BATCH * H2DIM + b * S_LEN + s] =
            __expf(g_wraw[b * S_LEN + s] - M) * invL;
    }
}

// ---------------------------------------------------------------------------
extern "C" void kernel_launch(void* const* d_in, const int* in_sizes, int n_in,
                              void* d_out, int out_size)
{
    const float* enc    = (const float*)d_in[0];
    const float* state  = (const float*)d_in[1];
    const float* attn_w = (const float*)d_in[3];
    const float* attn_b = (const float*)d_in[4];
    float* out = (float*)d_out;

    cudaFuncSetAttribute(k_mainpass,
        cudaFuncAttributeMaxDynamicSharedMemorySize, MAIN_SMEM);

    k_altered<<<256, 256>>>(state, attn_w, attn_b);

    // PDL: mainpass may start while k_altered drains; it prefetches enc via
    // TMA, then cudaGridDependencySynchronize() gates the g_alt read.
    cudaLaunchConfig_t cfg = {};
    cfg.gridDim = dim3(NBLK, 1, 1);
    cfg.blockDim = dim3(512, 1, 1);
    cfg.dynamicSmemBytes = MAIN_SMEM;
    cfg.stream = 0;
    cudaLaunchAttribute attrs[1];
    attrs[0].id = cudaLaunchAttributeProgrammaticStreamSerialization;
    attrs[0].val.programmaticStreamSerializationAllowed = 1;
    cfg.attrs = attrs;
    cfg.numAttrs = 1;
    cudaLaunchKernelEx(&cfg, k_mainpass, enc);

    k_finish<<<dim3(BATCH, 24), 512>>>(out);
}